// round 3
// baseline (speedup 1.0000x reference)
#include <cuda_runtime.h>
#include <cstdint>

#define NN    8192
#define FIN   256
#define FOUT  128
#define SLOPE 0.01f

// Scratch (device globals: no allocation allowed in kernel_launch)
__device__ float g_Wh[NN * FOUT];   // 4 MB
__device__ float g_src[NN];
__device__ float g_dst[NN];
__device__ float g_dstmax;

// ---------------------------------------------------------------------------
// Kernel A: Wh = h @ W  (8192x256 @ 256x128), plus src = Wh@a[:128],
// dst = Wh@a[128:]. 128 CTAs x 256 threads, BM=64 rows/CTA, k-chunk=32.
// Static smem: 64*33*4 + 32*128*4 + 256*4 = 25,856 B (< 48 KB).
// ---------------------------------------------------------------------------
__global__ __launch_bounds__(256) void wh_kernel(const float* __restrict__ h,
                                                 const float* __restrict__ W,
                                                 const float* __restrict__ a) {
    __shared__ float h_s[64][33];
    __shared__ float W_s[32][FOUT];
    __shared__ float a_s[2 * FOUT];

    const int t  = threadIdx.x;
    const int i0 = blockIdx.x * 64;
    a_s[t] = a[t];                      // 256 threads cover 256 values

    float C[4][8];
#pragma unroll
    for (int r = 0; r < 4; r++)
#pragma unroll
        for (int c = 0; c < 8; c++) C[r][c] = 0.f;

    const int tr = t >> 4;              // 0..15 (row group of 4)
    const int tc = t & 15;              // 0..15 (col group of 8)

    for (int k0 = 0; k0 < FIN; k0 += 32) {
        {   // h tile 64x32: 2048 floats / 256 thr = 8 floats (2 float4) each
            int row = t >> 2, colb = (t & 3) * 8;
            const float4* s4 =
                reinterpret_cast<const float4*>(h + (size_t)(i0 + row) * FIN + k0 + colb);
#pragma unroll
            for (int q = 0; q < 2; q++) {
                float4 v = s4[q];
                h_s[row][colb + 4 * q + 0] = v.x;
                h_s[row][colb + 4 * q + 1] = v.y;
                h_s[row][colb + 4 * q + 2] = v.z;
                h_s[row][colb + 4 * q + 3] = v.w;
            }
        }
        {   // W tile 32x128: 4096 floats / 256 thr = 16 floats (4 float4) each
            int row = t >> 3, colb = (t & 7) * 16;
            const float4* s4 =
                reinterpret_cast<const float4*>(W + (size_t)(k0 + row) * FOUT + colb);
            float4* d4 = reinterpret_cast<float4*>(&W_s[row][colb]);
#pragma unroll
            for (int q = 0; q < 4; q++) d4[q] = s4[q];
        }
        __syncthreads();

#pragma unroll
        for (int kk = 0; kk < 32; kk++) {
            float av[4];
#pragma unroll
            for (int r = 0; r < 4; r++) av[r] = h_s[tr * 4 + r][kk];
            float4 b0 = *reinterpret_cast<const float4*>(&W_s[kk][tc * 8]);
            float4 b1 = *reinterpret_cast<const float4*>(&W_s[kk][tc * 8 + 4]);
            float bv[8] = {b0.x, b0.y, b0.z, b0.w, b1.x, b1.y, b1.z, b1.w};
#pragma unroll
            for (int r = 0; r < 4; r++)
#pragma unroll
                for (int c = 0; c < 8; c++) C[r][c] += av[r] * bv[c];
        }
        __syncthreads();
    }

    // Write Wh; fold in src/dst partial dot-products
    float sp[4], dp[4];
#pragma unroll
    for (int r = 0; r < 4; r++) { sp[r] = 0.f; dp[r] = 0.f; }
#pragma unroll
    for (int r = 0; r < 4; r++) {
        int row = i0 + tr * 4 + r;
#pragma unroll
        for (int c = 0; c < 8; c++) {
            int col = tc * 8 + c;
            sp[r] += C[r][c] * a_s[col];
            dp[r] += C[r][c] * a_s[FOUT + col];
        }
        float4* o = reinterpret_cast<float4*>(&g_Wh[(size_t)row * FOUT + tc * 8]);
        o[0] = make_float4(C[r][0], C[r][1], C[r][2], C[r][3]);
        o[1] = make_float4(C[r][4], C[r][5], C[r][6], C[r][7]);
    }
    // reduce across the 16 col-groups (width-16 shuffle, tr constant per group)
#pragma unroll
    for (int off = 8; off >= 1; off >>= 1) {
#pragma unroll
        for (int r = 0; r < 4; r++) {
            sp[r] += __shfl_down_sync(0xffffffffu, sp[r], off, 16);
            dp[r] += __shfl_down_sync(0xffffffffu, dp[r], off, 16);
        }
    }
    if (tc == 0) {
#pragma unroll
        for (int r = 0; r < 4; r++) {
            g_src[i0 + tr * 4 + r] = sp[r];
            g_dst[i0 + tr * 4 + r] = dp[r];
        }
    }
}

// ---------------------------------------------------------------------------
// Kernel B: global max of dst (fixed softmax upper bound)
// ---------------------------------------------------------------------------
__global__ __launch_bounds__(256) void dstmax_kernel() {
    __shared__ float red[256];
    int t = threadIdx.x;
    float m = -1e30f;
    for (int i = t; i < NN; i += 256) m = fmaxf(m, g_dst[i]);
    red[t] = m;
    __syncthreads();
    for (int s = 128; s > 0; s >>= 1) {
        if (t < s) red[t] = fmaxf(red[t], red[t + s]);
        __syncthreads();
    }
    if (t == 0) g_dstmax = red[0];
}

// ---------------------------------------------------------------------------
// Kernel C: fused masked softmax + (att @ Wh).
// 128 CTAs, BM=64 rows each; j-tiles of 64. Single-pass softmax with fixed
// per-row upper bound m_i = lrelu(src_i + max_j dst_j).
// Dynamic smem: 64*65 + 64*128 + 64 + 64 floats = 49,920 B.
// ---------------------------------------------------------------------------
__global__ __launch_bounds__(256) void attn_kernel(const int* __restrict__ adj,
                                                   float* __restrict__ out) {
    extern __shared__ float smem[];
    float* p_s   = smem;                 // [64][65]
    float* wh_s  = smem + 64 * 65;       // [64][128]
    float* dst_s = wh_s + 64 * FOUT;     // [64]
    float* l_s   = dst_s + 64;           // [64]

    const int t  = threadIdx.x;
    const int i0 = blockIdx.x * 64;
    const int ii = t >> 2;               // phase-1 row this thread owns
    const int jb = (t & 3) * 16;         // phase-1 col base (16 contiguous)
    const int tr = t >> 4, tc = t & 15;  // GEMM thread mapping

    const float srow = g_src[i0 + ii];
    float mrow;
    {
        float x = srow + g_dstmax;
        mrow = x > 0.f ? x : SLOPE * x;
    }
    const int4* arow = reinterpret_cast<const int4*>(adj + (size_t)(i0 + ii) * NN);

    float lacc = 0.f;
    float C[4][8];
#pragma unroll
    for (int r = 0; r < 4; r++)
#pragma unroll
        for (int c = 0; c < 8; c++) C[r][c] = 0.f;

    // software-pipeline adj loads one tile ahead
    int4 anxt[4];
#pragma unroll
    for (int q = 0; q < 4; q++) anxt[q] = arow[(jb >> 2) + q];

    for (int j0 = 0; j0 < NN; j0 += 64) {
        int4 acur[4];
#pragma unroll
        for (int q = 0; q < 4; q++) acur[q] = anxt[q];
        if (j0 + 64 < NN) {
#pragma unroll
            for (int q = 0; q < 4; q++) anxt[q] = arow[((j0 + 64 + jb) >> 2) + q];
        }

        if (t < 64) dst_s[t] = g_dst[j0 + t];
        {   // Wh tile 64x128: 8192 floats / 256 thr = 32 floats (8 float4) each
            int row = t >> 2, colb = (t & 3) * 32;
            const float4* s4 =
                reinterpret_cast<const float4*>(g_Wh + (size_t)(j0 + row) * FOUT + colb);
            float4* d4 = reinterpret_cast<float4*>(&wh_s[row * FOUT + colb]);
#pragma unroll
            for (int q = 0; q < 8; q++) d4[q] = s4[q];
        }
        __syncthreads();

        // Phase 1: p tile (64x64) + partial row sums
        float lsum = 0.f;
#pragma unroll
        for (int q = 0; q < 4; q++) {
            int vals[4] = {acur[q].x, acur[q].y, acur[q].z, acur[q].w};
#pragma unroll
            for (int e = 0; e < 4; e++) {
                int   jj = jb + 4 * q + e;
                float x  = srow + dst_s[jj];
                float el = x > 0.f ? x : SLOPE * x;
                float p  = (vals[e] > 0) ? __expf(el - mrow) : 0.f;
                p_s[ii * 65 + jj] = p;
                lsum += p;
            }
        }
        lsum += __shfl_down_sync(0xffffffffu, lsum, 2, 4);
        lsum += __shfl_down_sync(0xffffffffu, lsum, 1, 4);
        if ((t & 3) == 0) lacc += lsum;
        __syncthreads();

        // Phase 2: C += P(64x64) @ WhTile(64x128)
#pragma unroll 16
        for (int kk = 0; kk < 64; kk++) {
            float av[4];
#pragma unroll
            for (int r = 0; r < 4; r++) av[r] = p_s[(tr * 4 + r) * 65 + kk];
            float4 b0 = *reinterpret_cast<const float4*>(&wh_s[kk * FOUT + tc * 8]);
            float4 b1 = *reinterpret_cast<const float4*>(&wh_s[kk * FOUT + tc * 8 + 4]);
            float bv[8] = {b0.x, b0.y, b0.z, b0.w, b1.x, b1.y, b1.z, b1.w};
#pragma unroll
            for (int r = 0; r < 4; r++)
#pragma unroll
                for (int c = 0; c < 8; c++) C[r][c] += av[r] * bv[c];
        }
        __syncthreads();
    }

    if ((t & 3) == 0) l_s[ii] = lacc;    // row ii owned by exactly one thread
    __syncthreads();

#pragma unroll
    for (int r = 0; r < 4; r++) {
        int   row = tr * 4 + r;
        float inv = 1.f / l_s[row];
        float4 o0 = make_float4(C[r][0] * inv, C[r][1] * inv, C[r][2] * inv, C[r][3] * inv);
        float4 o1 = make_float4(C[r][4] * inv, C[r][5] * inv, C[r][6] * inv, C[r][7] * inv);
        float4* o = reinterpret_cast<float4*>(out + (size_t)(i0 + row) * FOUT + tc * 8);
        o[0] = o0;
        o[1] = o1;
    }
}

// ---------------------------------------------------------------------------
extern "C" void kernel_launch(void* const* d_in, const int* in_sizes, int n_in,
                              void* d_out, int out_size) {
    // Identify inputs by element count (robust to metadata ordering):
    //   h: 8192*256 = 2,097,152 | adj: 8192*8192 = 67,108,864
    //   W: 256*128  =    32,768 | a:   2*128*1  =        256
    const float* h   = nullptr;
    const int*   adj = nullptr;
    const float* W   = nullptr;
    const float* a   = nullptr;
    for (int i = 0; i < n_in; i++) {
        switch (in_sizes[i]) {
            case NN * FIN:   h   = (const float*)d_in[i]; break;
            case NN * NN:    adj = (const int*)d_in[i];   break;  // note: NN*NN fits int
            case FIN * FOUT: W   = (const float*)d_in[i]; break;
            case 2 * FOUT:   a   = (const float*)d_in[i]; break;
            default: break;
        }
    }
    float* out = (float*)d_out;

    static const size_t ATTN_SMEM = (64 * 65 + 64 * FOUT + 64 + 64) * sizeof(float);
    cudaFuncSetAttribute(attn_kernel, cudaFuncAttributeMaxDynamicSharedMemorySize,
                         (int)ATTN_SMEM);

    wh_kernel<<<NN / 64, 256>>>(h, W, a);
    dstmax_kernel<<<1, 256>>>();
    attn_kernel<<<NN / 64, 256, ATTN_SMEM>>>(adj, out);
}

// round 7
// speedup vs baseline: 3.4084x; 3.4084x over previous
#include <cuda_runtime.h>
#include <cuda_bf16.h>
#include <cstdint>

#define NN    8192
#define FIN   256
#define FOUT  128
#define SLOPE 0.01f
#define BM    64             // rows per attn CTA
#define BK    64             // j-tile
#define NJ    (NN / BK)      // 128 tiles

// ---------------- device scratch ----------------
// Wh packed as m16n8k16 B-fragments: [K16 block][Nb(16)][lane(32)][2 u32]
// u32 index = ((K*16 + Nb)*32 + lane)*2 + sel   (2 MB total)
__device__ uint32_t g_WhF[NN * 64];
__device__ float g_src[NN], g_dst[NN];
__device__ float g_A[NN], g_C[NN];   // row factors: exp(s-m), exp(.01 s - m)
__device__ float g_B[NN], g_D[NN];   // col factors: exp(d),   exp(.01 d)
__device__ float g_dstmax;

__device__ __forceinline__ uint32_t pack_bf16x2(float lo, float hi) {
    __nv_bfloat162 h2 = __floats2bfloat162_rn(lo, hi);
    return *reinterpret_cast<uint32_t*>(&h2);
}
__device__ __forceinline__ float2 unpack_bf16x2(uint32_t v) {
    __nv_bfloat162 h2 = *reinterpret_cast<__nv_bfloat162*>(&v);
    return __bfloat1622float2(h2);
}
// D += A(16x16) @ B(16x8), bf16 in, fp32 accum (base ISA, sm_80+)
__device__ __forceinline__ void mma16816(float* d, uint32_t a0, uint32_t a1,
                                         uint32_t a2, uint32_t a3,
                                         uint32_t b0, uint32_t b1) {
    asm volatile(
        "mma.sync.aligned.m16n8k16.row.col.f32.bf16.bf16.f32 "
        "{%0,%1,%2,%3}, {%4,%5,%6,%7}, {%8,%9}, {%0,%1,%2,%3};"
        : "+f"(d[0]), "+f"(d[1]), "+f"(d[2]), "+f"(d[3])
        : "r"(a0), "r"(a1), "r"(a2), "r"(a3), "r"(b0), "r"(b1));
}

// ---------------------------------------------------------------------------
// Kernel A: Wh = h @ W; emits g_WhF (fragment-packed bf16) + g_src/g_dst.
// 128 CTAs x 256 thr, 64 rows each. Smem: 25856 + 16384 = 42240 B.
// ---------------------------------------------------------------------------
__global__ __launch_bounds__(256) void wh_kernel(const float* __restrict__ h,
                                                 const float* __restrict__ W,
                                                 const float* __restrict__ a) {
    __shared__ float h_s[64][33];
    __shared__ float W_s[32][FOUT];
    __shared__ float a_s[2 * FOUT];
    __shared__ uint32_t frag_s[4096];   // 16 KB fragment staging

    const int t  = threadIdx.x;
    const int i0 = blockIdx.x * 64;
    a_s[t] = a[t];

    float C[4][8];
#pragma unroll
    for (int r = 0; r < 4; r++)
#pragma unroll
        for (int c = 0; c < 8; c++) C[r][c] = 0.f;

    const int tr = t >> 4, tc = t & 15;

    for (int k0 = 0; k0 < FIN; k0 += 32) {
        {
            int row = t >> 2, colb = (t & 3) * 8;
            const float4* s4 =
                reinterpret_cast<const float4*>(h + (size_t)(i0 + row) * FIN + k0 + colb);
#pragma unroll
            for (int q = 0; q < 2; q++) {
                float4 v = s4[q];
                h_s[row][colb + 4 * q + 0] = v.x;
                h_s[row][colb + 4 * q + 1] = v.y;
                h_s[row][colb + 4 * q + 2] = v.z;
                h_s[row][colb + 4 * q + 3] = v.w;
            }
        }
        {
            int row = t >> 3, colb = (t & 7) * 16;
            const float4* s4 =
                reinterpret_cast<const float4*>(W + (size_t)(k0 + row) * FOUT + colb);
            float4* d4 = reinterpret_cast<float4*>(&W_s[row][colb]);
#pragma unroll
            for (int q = 0; q < 4; q++) d4[q] = s4[q];
        }
        __syncthreads();
#pragma unroll
        for (int kk = 0; kk < 32; kk++) {
            float av[4];
#pragma unroll
            for (int r = 0; r < 4; r++) av[r] = h_s[tr * 4 + r][kk];
            float4 b0 = *reinterpret_cast<const float4*>(&W_s[kk][tc * 8]);
            float4 b1 = *reinterpret_cast<const float4*>(&W_s[kk][tc * 8 + 4]);
            float bv[8] = {b0.x, b0.y, b0.z, b0.w, b1.x, b1.y, b1.z, b1.w};
#pragma unroll
            for (int r = 0; r < 4; r++)
#pragma unroll
                for (int c = 0; c < 8; c++) C[r][c] += av[r] * bv[c];
        }
        __syncthreads();
    }

    // src/dst partials
    float sp[4], dp[4];
#pragma unroll
    for (int r = 0; r < 4; r++) { sp[r] = 0.f; dp[r] = 0.f; }
#pragma unroll
    for (int r = 0; r < 4; r++)
#pragma unroll
        for (int c = 0; c < 8; c++) {
            int col = tc * 8 + c;
            sp[r] += C[r][c] * a_s[col];
            dp[r] += C[r][c] * a_s[FOUT + col];
        }
#pragma unroll
    for (int off = 8; off >= 1; off >>= 1) {
#pragma unroll
        for (int r = 0; r < 4; r++) {
            sp[r] += __shfl_down_sync(0xffffffffu, sp[r], off, 16);
            dp[r] += __shfl_down_sync(0xffffffffu, dp[r], off, 16);
        }
    }
    if (tc == 0) {
#pragma unroll
        for (int r = 0; r < 4; r++) {
            g_src[i0 + tr * 4 + r] = sp[r];
            g_dst[i0 + tr * 4 + r] = dp[r];
        }
    }

    // ---- pack Wh into B-fragment layout ----
    // Thread owns Wh rows (k dim) kk = tr*4 + {0..3}, cols (n dim) tc*8 + {0..7}.
    // B frag (m16n8k16): lane = n%8 * 4 + ((k%16)/2)%4 ; sel = (k%16)/8 ; value
    // = bf16x2( Wh[k][n], Wh[k+1][n] ), k even.
#pragma unroll
    for (int q = 0; q < 2; q++) {
        int kk   = tr * 4 + 2 * q;
        int Kloc = kk >> 4;            // 0..3
        int klo  = kk & 15;
        int sel  = klo >> 3;
        int tig  = (klo >> 1) & 3;
#pragma unroll
        for (int c = 0; c < 8; c++) {
            uint32_t v    = pack_bf16x2(C[2 * q][c], C[2 * q + 1][c]);
            int      lane = c * 4 + tig;
            frag_s[((Kloc * 16 + tc) * 32 + lane) * 2 + sel] = v;
        }
    }
    __syncthreads();
    {   // coalesced 16 KB store: this CTA owns K blocks i0/16..+3 -> u32 base i0*64
        uint4*       dst = reinterpret_cast<uint4*>(g_WhF + (size_t)i0 * 64);
        const uint4* src = reinterpret_cast<const uint4*>(frag_s);
#pragma unroll
        for (int i = 0; i < 4; i++) dst[t * 4 + i] = src[t * 4 + i];
    }
}

// ---------------------------------------------------------------------------
__global__ __launch_bounds__(256) void dstmax_kernel() {
    __shared__ float red[256];
    int t = threadIdx.x;
    float m = -1e30f;
    for (int i = t; i < NN; i += 256) m = fmaxf(m, g_dst[i]);
    red[t] = m;
    __syncthreads();
    for (int s = 128; s > 0; s >>= 1) {
        if (t < s) red[t] = fmaxf(red[t], red[t + s]);
        __syncthreads();
    }
    if (t == 0) g_dstmax = red[0];
}

__global__ __launch_bounds__(256) void vec_kernel() {
    int   i = blockIdx.x * 256 + threadIdx.x;
    float s = g_src[i], d = g_dst[i];
    float x = s + g_dstmax;
    float m = x > 0.f ? x : SLOPE * x;
    g_A[i] = __expf(s - m);
    g_C[i] = __expf(SLOPE * s - m);
    g_B[i] = __expf(d);
    g_D[i] = __expf(SLOPE * d);
}

// ---------------------------------------------------------------------------
// Kernel D: fused masked softmax + (att @ Wh) via mma.sync (bf16 HMMA).
// 128 CTAs x 256 thr. Warp w: wm = w&3 (16 rows), wn = w>>2 (64 cols).
// Smem: WhF 16384 + adj 64*68*4=17408 + vectors ~1 KB = ~35 KB static.
// ---------------------------------------------------------------------------
__global__ __launch_bounds__(256) void attn_kernel(const int* __restrict__ adj,
                                                   float* __restrict__ out) {
    __shared__ __align__(16) uint32_t whf_s[4096];      // B fragments for tile
    __shared__ __align__(16) int      adj_s[64 * 68];   // padded stride 68
    __shared__ __align__(16) float    dst_s[64], bf_s[64], df_s[64];
    __shared__ float l_s[64];

    const int t  = threadIdx.x;
    const int l  = t & 31;
    const int w  = t >> 5;
    const int wm = w & 3;        // m-tile
    const int wn = w >> 2;       // n-half
    const int i0 = blockIdx.x * BM;

    const int r0 = wm * 16 + (l >> 2);   // local rows
    const int r1 = r0 + 8;
    const int tig = l & 3;

    const float s0 = g_src[i0 + r0], A0 = g_A[i0 + r0], C0 = g_C[i0 + r0];
    const float s1 = g_src[i0 + r1], A1 = g_A[i0 + r1], C1 = g_C[i0 + r1];

    float acc[8][4];
#pragma unroll
    for (int nb = 0; nb < 8; nb++)
#pragma unroll
        for (int q = 0; q < 4; q++) acc[nb][q] = 0.f;
    float lacc0 = 0.f, lacc1 = 0.f;

    // staging identities
    const int ldrow = t >> 2;               // adj row this thread loads
    const int ldcol = (t & 3) * 16;
    const uint4* wf_g = reinterpret_cast<const uint4*>(g_WhF);

    // preload tile 0
    uint4 nW[4], nA[4];
    float nV = 0.f;
#pragma unroll
    for (int i = 0; i < 4; i++) nW[i] = wf_g[t * 4 + i];
    {
        const uint4* ap =
            reinterpret_cast<const uint4*>(adj + (size_t)(i0 + ldrow) * NN + ldcol);
#pragma unroll
        for (int i = 0; i < 4; i++) nA[i] = ap[i];
    }
    if (t < 64)       nV = g_dst[t];
    else if (t < 128) nV = g_B[t - 64];
    else if (t < 192) nV = g_D[t - 128];

    for (int jt = 0; jt < NJ; jt++) {
        const int j0 = jt * BK;

        // ---- stage current tile ----
#pragma unroll
        for (int i = 0; i < 4; i++)
            reinterpret_cast<uint4*>(whf_s)[t * 4 + i] = nW[i];
#pragma unroll
        for (int i = 0; i < 4; i++)
            *reinterpret_cast<int4*>(&adj_s[ldrow * 68 + ldcol + i * 4]) =
                *reinterpret_cast<int4*>(&nA[i]);
        if (t < 64)       dst_s[t]      = nV;
        else if (t < 128) bf_s[t - 64]  = nV;
        else if (t < 192) df_s[t - 128] = nV;
        __syncthreads();

        // ---- prefetch next tile ----
        if (jt + 1 < NJ) {
            const int jn = j0 + BK;
#pragma unroll
            for (int i = 0; i < 4; i++) nW[i] = wf_g[(size_t)(jt + 1) * 1024 + t * 4 + i];
            const uint4* ap =
                reinterpret_cast<const uint4*>(adj + (size_t)(i0 + ldrow) * NN + jn + ldcol);
#pragma unroll
            for (int i = 0; i < 4; i++) nA[i] = ap[i];
            if (t < 64)       nV = g_dst[jn + t];
            else if (t < 128) nV = g_B[jn + t - 64];
            else if (t < 192) nV = g_D[jn + t - 128];
        }

        // ---- compute: 4 k-steps of m16n8k16 ----
#pragma unroll
        for (int s = 0; s < 4; s++) {
            const int c01 = s * 16 + tig * 2;
            const int c23 = c01 + 8;
            float2 d0 = *reinterpret_cast<const float2*>(&dst_s[c01]);
            float2 d1 = *reinterpret_cast<const float2*>(&dst_s[c23]);
            float2 B0 = *reinterpret_cast<const float2*>(&bf_s[c01]);
            float2 B1 = *reinterpret_cast<const float2*>(&bf_s[c23]);
            float2 D0 = *reinterpret_cast<const float2*>(&df_s[c01]);
            float2 D1 = *reinterpret_cast<const float2*>(&df_s[c23]);
            int2 m00 = *reinterpret_cast<const int2*>(&adj_s[r0 * 68 + c01]);
            int2 m10 = *reinterpret_cast<const int2*>(&adj_s[r1 * 68 + c01]);
            int2 m01 = *reinterpret_cast<const int2*>(&adj_s[r0 * 68 + c23]);
            int2 m11 = *reinterpret_cast<const int2*>(&adj_s[r1 * 68 + c23]);

            float pa = (m00.x > 0) ? ((s0 + d0.x >= 0.f) ? A0 * B0.x : C0 * D0.x) : 0.f;
            float pb = (m00.y > 0) ? ((s0 + d0.y >= 0.f) ? A0 * B0.y : C0 * D0.y) : 0.f;
            float pc = (m10.x > 0) ? ((s1 + d0.x >= 0.f) ? A1 * B0.x : C1 * D0.x) : 0.f;
            float pd = (m10.y > 0) ? ((s1 + d0.y >= 0.f) ? A1 * B0.y : C1 * D0.y) : 0.f;
            float pe = (m01.x > 0) ? ((s0 + d1.x >= 0.f) ? A0 * B1.x : C0 * D1.x) : 0.f;
            float pf = (m01.y > 0) ? ((s0 + d1.y >= 0.f) ? A0 * B1.y : C0 * D1.y) : 0.f;
            float pg = (m11.x > 0) ? ((s1 + d1.x >= 0.f) ? A1 * B1.x : C1 * D1.x) : 0.f;
            float ph = (m11.y > 0) ? ((s1 + d1.y >= 0.f) ? A1 * B1.y : C1 * D1.y) : 0.f;

            uint32_t a0 = pack_bf16x2(pa, pb);
            uint32_t a1 = pack_bf16x2(pc, pd);
            uint32_t a2 = pack_bf16x2(pe, pf);
            uint32_t a3 = pack_bf16x2(pg, ph);

            if (wn == 0) {   // row sums from the ROUNDED values (numerics match)
                float2 u;
                u = unpack_bf16x2(a0); lacc0 += u.x + u.y;
                u = unpack_bf16x2(a2); lacc0 += u.x + u.y;
                u = unpack_bf16x2(a1); lacc1 += u.x + u.y;
                u = unpack_bf16x2(a3); lacc1 += u.x + u.y;
            }

#pragma unroll
            for (int nb = 0; nb < 8; nb++) {
                uint2 b = reinterpret_cast<const uint2*>(whf_s)
                              [(s * 16 + wn * 8 + nb) * 32 + l];
                mma16816(acc[nb], a0, a1, a2, a3, b.x, b.y);
            }
        }
        __syncthreads();
    }

    // row sums -> l_s
    if (wn == 0) {
        lacc0 += __shfl_down_sync(0xffffffffu, lacc0, 2, 4);
        lacc0 += __shfl_down_sync(0xffffffffu, lacc0, 1, 4);
        lacc1 += __shfl_down_sync(0xffffffffu, lacc1, 2, 4);
        lacc1 += __shfl_down_sync(0xffffffffu, lacc1, 1, 4);
        if (tig == 0) { l_s[r0] = lacc0; l_s[r1] = lacc1; }
    }
    __syncthreads();

    const float inv0 = 1.f / l_s[r0];
    const float inv1 = 1.f / l_s[r1];
#pragma unroll
    for (int nb = 0; nb < 8; nb++) {
        int n = wn * 64 + nb * 8 + tig * 2;
        *reinterpret_cast<float2*>(out + (size_t)(i0 + r0) * FOUT + n) =
            make_float2(acc[nb][0] * inv0, acc[nb][1] * inv0);
        *reinterpret_cast<float2*>(out + (size_t)(i0 + r1) * FOUT + n) =
            make_float2(acc[nb][2] * inv1, acc[nb][3] * inv1);
    }
}

// ---------------------------------------------------------------------------
extern "C" void kernel_launch(void* const* d_in, const int* in_sizes, int n_in,
                              void* d_out, int out_size) {
    const float* h   = nullptr;
    const int*   adj = nullptr;
    const float* W   = nullptr;
    const float* a   = nullptr;
    for (int i = 0; i < n_in; i++) {
        switch (in_sizes[i]) {
            case NN * FIN:   h   = (const float*)d_in[i]; break;
            case NN * NN:    adj = (const int*)d_in[i];   break;
            case FIN * FOUT: W   = (const float*)d_in[i]; break;
            case 2 * FOUT:   a   = (const float*)d_in[i]; break;
            default: break;
        }
    }
    float* out = (float*)d_out;

    wh_kernel<<<NN / 64, 256>>>(h, W, a);
    dstmax_kernel<<<1, 256>>>();
    vec_kernel<<<NN / 256, 256>>>();
    attn_kernel<<<NN / BM, 256>>>(adj, out);
}

// round 8
// speedup vs baseline: 4.6878x; 1.3754x over previous
#include <cuda_runtime.h>
#include <cuda_bf16.h>
#include <cstdint>

#define NN    8192
#define FIN   256
#define FOUT  128
#define SLOPE 0.01f
#define BM    64             // rows per attn CTA
#define BK    64             // j-tile
#define NJ    (NN / BK)      // 128 tiles

// ---------------- device scratch ----------------
// Wh packed as m16n8k16 B-fragments: [K16 block][Nb(16)][lane(32)][2 u32]
__device__ uint32_t g_WhF[NN * 64];
__device__ float g_src[NN], g_dst[NN];
__device__ float g_A[NN], g_C[NN];   // row factors: exp(s-m), exp(.01 s - m)
__device__ float g_B[NN], g_D[NN];   // col factors: exp(d),   exp(.01 d)
__device__ float g_dstmax;

__device__ __forceinline__ uint32_t pack_bf16x2(float lo, float hi) {
    __nv_bfloat162 h2 = __floats2bfloat162_rn(lo, hi);
    return *reinterpret_cast<uint32_t*>(&h2);
}
// D += A(16x16) @ B(16x8), bf16 in, fp32 accum (base ISA)
__device__ __forceinline__ void mma16816(float* d, uint32_t a0, uint32_t a1,
                                         uint32_t a2, uint32_t a3,
                                         uint32_t b0, uint32_t b1) {
    asm volatile(
        "mma.sync.aligned.m16n8k16.row.col.f32.bf16.bf16.f32 "
        "{%0,%1,%2,%3}, {%4,%5,%6,%7}, {%8,%9}, {%0,%1,%2,%3};"
        : "+f"(d[0]), "+f"(d[1]), "+f"(d[2]), "+f"(d[3])
        : "r"(a0), "r"(a1), "r"(a2), "r"(a3), "r"(b0), "r"(b1));
}

// ---------------------------------------------------------------------------
// Kernel A: Wh = h @ W; emits g_WhF (fragment-packed bf16) + g_src/g_dst.
// ---------------------------------------------------------------------------
__global__ __launch_bounds__(256) void wh_kernel(const float* __restrict__ h,
                                                 const float* __restrict__ W,
                                                 const float* __restrict__ a) {
    __shared__ float h_s[64][33];
    __shared__ float W_s[32][FOUT];
    __shared__ float a_s[2 * FOUT];
    __shared__ uint32_t frag_s[4096];   // 16 KB fragment staging

    const int t  = threadIdx.x;
    const int i0 = blockIdx.x * 64;
    a_s[t] = a[t];

    float C[4][8];
#pragma unroll
    for (int r = 0; r < 4; r++)
#pragma unroll
        for (int c = 0; c < 8; c++) C[r][c] = 0.f;

    const int tr = t >> 4, tc = t & 15;

    for (int k0 = 0; k0 < FIN; k0 += 32) {
        {
            int row = t >> 2, colb = (t & 3) * 8;
            const float4* s4 =
                reinterpret_cast<const float4*>(h + (size_t)(i0 + row) * FIN + k0 + colb);
#pragma unroll
            for (int q = 0; q < 2; q++) {
                float4 v = s4[q];
                h_s[row][colb + 4 * q + 0] = v.x;
                h_s[row][colb + 4 * q + 1] = v.y;
                h_s[row][colb + 4 * q + 2] = v.z;
                h_s[row][colb + 4 * q + 3] = v.w;
            }
        }
        {
            int row = t >> 3, colb = (t & 7) * 16;
            const float4* s4 =
                reinterpret_cast<const float4*>(W + (size_t)(k0 + row) * FOUT + colb);
            float4* d4 = reinterpret_cast<float4*>(&W_s[row][colb]);
#pragma unroll
            for (int q = 0; q < 4; q++) d4[q] = s4[q];
        }
        __syncthreads();
#pragma unroll
        for (int kk = 0; kk < 32; kk++) {
            float av[4];
#pragma unroll
            for (int r = 0; r < 4; r++) av[r] = h_s[tr * 4 + r][kk];
            float4 b0 = *reinterpret_cast<const float4*>(&W_s[kk][tc * 8]);
            float4 b1 = *reinterpret_cast<const float4*>(&W_s[kk][tc * 8 + 4]);
            float bv[8] = {b0.x, b0.y, b0.z, b0.w, b1.x, b1.y, b1.z, b1.w};
#pragma unroll
            for (int r = 0; r < 4; r++)
#pragma unroll
                for (int c = 0; c < 8; c++) C[r][c] += av[r] * bv[c];
        }
        __syncthreads();
    }

    float sp[4], dp[4];
#pragma unroll
    for (int r = 0; r < 4; r++) { sp[r] = 0.f; dp[r] = 0.f; }
#pragma unroll
    for (int r = 0; r < 4; r++)
#pragma unroll
        for (int c = 0; c < 8; c++) {
            int col = tc * 8 + c;
            sp[r] += C[r][c] * a_s[col];
            dp[r] += C[r][c] * a_s[FOUT + col];
        }
#pragma unroll
    for (int off = 8; off >= 1; off >>= 1) {
#pragma unroll
        for (int r = 0; r < 4; r++) {
            sp[r] += __shfl_down_sync(0xffffffffu, sp[r], off, 16);
            dp[r] += __shfl_down_sync(0xffffffffu, dp[r], off, 16);
        }
    }
    if (tc == 0) {
#pragma unroll
        for (int r = 0; r < 4; r++) {
            g_src[i0 + tr * 4 + r] = sp[r];
            g_dst[i0 + tr * 4 + r] = dp[r];
        }
    }

    // pack Wh into B-fragment layout (see R7 derivation)
#pragma unroll
    for (int q = 0; q < 2; q++) {
        int kk   = tr * 4 + 2 * q;
        int Kloc = kk >> 4;
        int klo  = kk & 15;
        int sel  = klo >> 3;
        int tig  = (klo >> 1) & 3;
#pragma unroll
        for (int c = 0; c < 8; c++) {
            uint32_t v    = pack_bf16x2(C[2 * q][c], C[2 * q + 1][c]);
            int      lane = c * 4 + tig;
            frag_s[((Kloc * 16 + tc) * 32 + lane) * 2 + sel] = v;
        }
    }
    __syncthreads();
    {
        uint4*       dst = reinterpret_cast<uint4*>(g_WhF + (size_t)i0 * 64);
        const uint4* src = reinterpret_cast<const uint4*>(frag_s);
#pragma unroll
        for (int i = 0; i < 4; i++) dst[t * 4 + i] = src[t * 4 + i];
    }
}

// ---------------------------------------------------------------------------
__global__ __launch_bounds__(256) void dstmax_kernel() {
    __shared__ float red[256];
    int t = threadIdx.x;
    float m = -1e30f;
    for (int i = t; i < NN; i += 256) m = fmaxf(m, g_dst[i]);
    red[t] = m;
    __syncthreads();
    for (int s = 128; s > 0; s >>= 1) {
        if (t < s) red[t] = fmaxf(red[t], red[t + s]);
        __syncthreads();
    }
    if (t == 0) g_dstmax = red[0];
}

__global__ __launch_bounds__(256) void vec_kernel() {
    int   i = blockIdx.x * 256 + threadIdx.x;
    float s = g_src[i], d = g_dst[i];
    float x = s + g_dstmax;
    float m = x > 0.f ? x : SLOPE * x;
    g_A[i] = __expf(s - m);
    g_C[i] = __expf(SLOPE * s - m);
    g_B[i] = __expf(d);
    g_D[i] = __expf(SLOPE * d);
}

// ---------------------------------------------------------------------------
// Kernel D: fused masked softmax + (att @ Wh), bf16 HMMA.
// 128 CTAs x 512 thr (16 warps): wm = w&3 (16 rows), wn = (w>>2)&1 (64 cols),
// sh = w>>3 (2 of 4 k16-steps). Row sums via ones-column mma (wn==0 only).
// ---------------------------------------------------------------------------
__global__ __launch_bounds__(512, 1) void attn_kernel(const int* __restrict__ adj,
                                                      float* __restrict__ out) {
    // big_s: [whf 16384 B][adj 64*68*4 = 17408 B]; reused as fp32 reduce buffer
    __shared__ __align__(16) char  big_s[16384 + 17408];
    __shared__ __align__(16) float dst_s[64], bf_s[64], df_s[64];
    __shared__ __align__(16) float l_red[4 * 128];
    __shared__ float l_s[64];

    uint32_t* whf_s = reinterpret_cast<uint32_t*>(big_s);
    int*      adj_s = reinterpret_cast<int*>(big_s + 16384);
    float*    red_s = reinterpret_cast<float*>(big_s);       // post-loop alias

    const int t  = threadIdx.x;
    const int l  = t & 31;
    const int w  = t >> 5;
    const int wm = w & 3;
    const int wn = (w >> 2) & 1;
    const int sh = w >> 3;
    const int i0 = blockIdx.x * BM;

    const int r0  = wm * 16 + (l >> 2);
    const int r1  = r0 + 8;
    const int tig = l & 3;

    const float s0 = g_src[i0 + r0], A0 = g_A[i0 + r0], C0 = g_C[i0 + r0];
    const float s1 = g_src[i0 + r1], A1 = g_A[i0 + r1], C1 = g_C[i0 + r1];

    const uint32_t ones_b = (l < 4) ? 0x3F803F80u : 0u;  // B col 0 = 1.0

    float acc[8][4];
#pragma unroll
    for (int nb = 0; nb < 8; nb++)
#pragma unroll
        for (int q = 0; q < 4; q++) acc[nb][q] = 0.f;
    float lacc[4] = {0.f, 0.f, 0.f, 0.f};

    // staging identities (512 threads)
    const int arow_i = t >> 3;           // adj row 0..63
    const int acol_i = (t & 7) * 8;      // 8 ints (2 int4)
    const uint4* wf_g = reinterpret_cast<const uint4*>(g_WhF);

    // preload tile 0
    uint4 nW[2], nA[2];
    float nV = 0.f;
#pragma unroll
    for (int i = 0; i < 2; i++) nW[i] = wf_g[t * 2 + i];
    {
        const uint4* ap =
            reinterpret_cast<const uint4*>(adj + (size_t)(i0 + arow_i) * NN + acol_i);
        nA[0] = ap[0];
        nA[1] = ap[1];
    }
    if (t < 64)       nV = g_dst[t];
    else if (t < 128) nV = g_B[t - 64];
    else if (t < 192) nV = g_D[t - 128];

    for (int jt = 0; jt < NJ; jt++) {
        // ---- stage current tile ----
#pragma unroll
        for (int i = 0; i < 2; i++)
            reinterpret_cast<uint4*>(whf_s)[t * 2 + i] = nW[i];
#pragma unroll
        for (int i = 0; i < 2; i++)
            *reinterpret_cast<int4*>(&adj_s[arow_i * 68 + acol_i + i * 4]) =
                *reinterpret_cast<int4*>(&nA[i]);
        if (t < 64)       dst_s[t]      = nV;
        else if (t < 128) bf_s[t - 64]  = nV;
        else if (t < 192) df_s[t - 128] = nV;
        __syncthreads();

        // ---- prefetch next tile ----
        if (jt + 1 < NJ) {
            const int jn = (jt + 1) * BK;
#pragma unroll
            for (int i = 0; i < 2; i++)
                nW[i] = wf_g[(size_t)(jt + 1) * 1024 + t * 2 + i];
            const uint4* ap =
                reinterpret_cast<const uint4*>(adj + (size_t)(i0 + arow_i) * NN + jn + acol_i);
            nA[0] = ap[0];
            nA[1] = ap[1];
            if (t < 64)       nV = g_dst[jn + t];
            else if (t < 128) nV = g_B[jn + t - 64];
            else if (t < 192) nV = g_D[jn + t - 128];
        }

        // ---- compute: this warp's 2 k16-steps ----
#pragma unroll
        for (int q = 0; q < 2; q++) {
            const int s   = sh * 2 + q;
            const int c01 = s * 16 + tig * 2;
            const int c23 = c01 + 8;
            float2 d0 = *reinterpret_cast<const float2*>(&dst_s[c01]);
            float2 d1 = *reinterpret_cast<const float2*>(&dst_s[c23]);
            float2 B0 = *reinterpret_cast<const float2*>(&bf_s[c01]);
            float2 B1 = *reinterpret_cast<const float2*>(&bf_s[c23]);
            float2 D0 = *reinterpret_cast<const float2*>(&df_s[c01]);
            float2 D1 = *reinterpret_cast<const float2*>(&df_s[c23]);
            int2 m00 = *reinterpret_cast<const int2*>(&adj_s[r0 * 68 + c01]);
            int2 m10 = *reinterpret_cast<const int2*>(&adj_s[r1 * 68 + c01]);
            int2 m01 = *reinterpret_cast<const int2*>(&adj_s[r0 * 68 + c23]);
            int2 m11 = *reinterpret_cast<const int2*>(&adj_s[r1 * 68 + c23]);

            float pa = (m00.x > 0) ? ((s0 + d0.x >= 0.f) ? A0 * B0.x : C0 * D0.x) : 0.f;
            float pb = (m00.y > 0) ? ((s0 + d0.y >= 0.f) ? A0 * B0.y : C0 * D0.y) : 0.f;
            float pc = (m10.x > 0) ? ((s1 + d0.x >= 0.f) ? A1 * B0.x : C1 * D0.x) : 0.f;
            float pd = (m10.y > 0) ? ((s1 + d0.y >= 0.f) ? A1 * B0.y : C1 * D0.y) : 0.f;
            float pe = (m01.x > 0) ? ((s0 + d1.x >= 0.f) ? A0 * B1.x : C0 * D1.x) : 0.f;
            float pf = (m01.y > 0) ? ((s0 + d1.y >= 0.f) ? A0 * B1.y : C0 * D1.y) : 0.f;
            float pg = (m11.x > 0) ? ((s1 + d1.x >= 0.f) ? A1 * B1.x : C1 * D1.x) : 0.f;
            float ph = (m11.y > 0) ? ((s1 + d1.y >= 0.f) ? A1 * B1.y : C1 * D1.y) : 0.f;

            uint32_t a0 = pack_bf16x2(pa, pb);
            uint32_t a1 = pack_bf16x2(pc, pd);
            uint32_t a2 = pack_bf16x2(pe, pf);
            uint32_t a3 = pack_bf16x2(pg, ph);

            if (wn == 0)   // row sums of ROUNDED P via ones-column mma
                mma16816(lacc, a0, a1, a2, a3, ones_b, ones_b);

#pragma unroll
            for (int nb = 0; nb < 8; nb++) {
                uint2 b = reinterpret_cast<const uint2*>(whf_s)
                              [(s * 16 + wn * 8 + nb) * 32 + l];
                mma16816(acc[nb], a0, a1, a2, a3, b.x, b.y);
            }
        }
        __syncthreads();
    }

    // ---- combine k-split halves ----
    const int pair = wm * 2 + wn;                 // 0..7
    if (sh == 1) {
#pragma unroll
        for (int nb = 0; nb < 8; nb++)
            *reinterpret_cast<float4*>(&red_s[pair * 1024 + nb * 128 + l * 4]) =
                *reinterpret_cast<const float4*>(acc[nb]);
        if (wn == 0)
            *reinterpret_cast<float4*>(&l_red[wm * 128 + l * 4]) =
                *reinterpret_cast<const float4*>(lacc);
    }
    __syncthreads();
    if (sh == 0) {
#pragma unroll
        for (int nb = 0; nb < 8; nb++) {
            float4 v = *reinterpret_cast<const float4*>(&red_s[pair * 1024 + nb * 128 + l * 4]);
            acc[nb][0] += v.x; acc[nb][1] += v.y; acc[nb][2] += v.z; acc[nb][3] += v.w;
        }
        if (wn == 0) {
            float4 v = *reinterpret_cast<const float4*>(&l_red[wm * 128 + l * 4]);
            lacc[0] += v.x; lacc[2] += v.z;
            if (tig == 0) { l_s[r0] = lacc[0]; l_s[r1] = lacc[2]; }
        }
    }
    __syncthreads();

    if (sh == 0) {
        const float inv0 = 1.f / l_s[r0];
        const float inv1 = 1.f / l_s[r1];
#pragma unroll
        for (int nb = 0; nb < 8; nb++) {
            int n = wn * 64 + nb * 8 + tig * 2;
            *reinterpret_cast<float2*>(out + (size_t)(i0 + r0) * FOUT + n) =
                make_float2(acc[nb][0] * inv0, acc[nb][1] * inv0);
            *reinterpret_cast<float2*>(out + (size_t)(i0 + r1) * FOUT + n) =
                make_float2(acc[nb][2] * inv1, acc[nb][3] * inv1);
        }
    }
}

// ---------------------------------------------------------------------------
extern "C" void kernel_launch(void* const* d_in, const int* in_sizes, int n_in,
                              void* d_out, int out_size) {
    const float* h   = nullptr;
    const int*   adj = nullptr;
    const float* W   = nullptr;
    const float* a   = nullptr;
    for (int i = 0; i < n_in; i++) {
        switch (in_sizes[i]) {
            case NN * FIN:   h   = (const float*)d_in[i]; break;
            case NN * NN:    adj = (const int*)d_in[i];   break;
            case FIN * FOUT: W   = (const float*)d_in[i]; break;
            case 2 * FOUT:   a   = (const float*)d_in[i]; break;
            default: break;
        }
    }
    float* out = (float*)d_out;

    wh_kernel<<<NN / 64, 256>>>(h, W, a);
    dstmax_kernel<<<1, 256>>>();
    vec_kernel<<<NN / 256, 256>>>();
    attn_kernel<<<NN / BM, 512>>>(adj, out);
}